// round 14
// baseline (speedup 1.0000x reference)
#include <cuda_runtime.h>
#include <cstdint>

// DirectConv2d full cross-correlation (pad=2) via Winograd F(2x2,3x3), int8 IMMA.
//   inp [32,128,56,60] f32 (0..3), wgt [256,128,3,3] f32 (0..2), out [32,256,58,62] f32
//
// U = Ghat g Ghat^T (|U|<=18, s8), V = B^T d B (|V|<=12, s8),
// out = (1/4) * sum_t w_t(pix) M_t with integer w in {0,+-1,+-2,+-4} — all exact.
//
// R14 vs R13 (190us main): (1) B raw quads fetched by cp.async into a per-thread
// slot ring and combined AFTER compute (latency hidden, no regs held across MMAs);
// (2) all-integer output accumulation (no I2F/FFMA tail). Fragment maps unchanged.

#define OH 58
#define OW 62
#define PX 66

__device__ __align__(16) signed char g_p8[(size_t)32 * 60 * PX * 128];   // 16.2 MB
__device__ __align__(16) signed char g_Ufrag[16 * 2 * 4 * 2 * 4 * 512];  // 512 KB

// ---------------- combined pre-pass (identical to R13, validated) ----------------
__global__ __launch_bounds__(256)
void prep_all(const float* __restrict__ inp, const float* __restrict__ wgt)
{
    if (blockIdx.x >= 1920) {
        int idx = (blockIdx.x - 1920) * 256 + threadIdx.x;
        int ci = idx & 127;
        int co = (idx >> 7) & 255;
        int t  = idx >> 15;
        int i = t >> 2, j = t & 3;
        const float* g = wgt + (size_t)(co * 128 + ci) * 9;
        float hv[3];
#pragma unroll
        for (int kw = 0; kw < 3; kw++) {
            float g0 = g[kw], g1 = g[3 + kw], g2 = g[6 + kw];
            hv[kw] = (i == 0) ? g0 : (i == 1) ? g0 + g1 + g2
                   : (i == 2) ? g0 - g1 + g2 : g2;
        }
        float u = (j == 0) ? hv[0] : (j == 1) ? hv[0] + hv[1] + hv[2]
                : (j == 2) ? hv[0] - hv[1] + hv[2] : hv[2];
        int coB = co >> 7, wm = (co >> 5) & 3;
        int r5 = co & 31,  mi = r5 >> 4, rr = r5 & 15;
        int qb = rr >> 3,  lh = rr & 7;
        int ks = ci >> 5,  cr = ci & 31;
        int qh = cr >> 4,  cl = cr & 15;
        int l  = lh * 4 + (cl >> 2);
        int q  = qh * 2 + qb;
        g_Ufrag[(size_t)(((((t * 2 + coB) * 4 + wm) * 2 + mi) * 4 + ks)) * 512
                + l * 16 + q * 4 + (cl & 3)] = (signed char)__float2int_rn(u);
        return;
    }
    __shared__ signed char sh[PX][144];
    const int y   = blockIdx.x % 60;
    const int img = blockIdx.x / 60;
    const int tid = threadIdx.x;
    const int ih  = y - 2;
    const bool rowOK = (unsigned)ih < 56u;
    for (int it = 0; it < 33; it++) {
        int idx = it * 256 + tid;
        int x  = idx % PX;
        int ci = idx / PX;
        int iw = x - 2;
        float v = 0.0f;
        if (rowOK && (unsigned)iw < 60u)
            v = inp[((size_t)(img * 128 + ci) * 56 + ih) * 60 + iw];
        sh[x][ci] = (signed char)__float2int_rn(v);
    }
    __syncthreads();
    signed char* const ob = g_p8 + ((size_t)(img * 60 + y) * PX) * 128;
    for (int it = 0; it < 3; it++) {
        int idx = it * 256 + tid;
        if (idx >= PX * 8) break;
        int x = idx >> 3, c16 = idx & 7;
        *(uint4*)(ob + x * 128 + c16 * 16) = *(const uint4*)(&sh[x][c16 * 16]);
    }
}

// ---------------- PTX helpers ----------------
#define CP16(dst, src) \
    asm volatile("cp.async.cg.shared.global [%0], [%1], 16;" :: "r"(dst), "l"(src))
#define CP_COMMIT() asm volatile("cp.async.commit_group;" ::: "memory")
#define CP_WAIT0()  asm volatile("cp.async.wait_group 0;" ::: "memory")

#define LDSM_X4(R, addr)                                                        \
    asm volatile("ldmatrix.sync.aligned.m8n8.x4.shared.b16 {%0,%1,%2,%3}, [%4];"\
                 : "=r"((R)[0]), "=r"((R)[1]), "=r"((R)[2]), "=r"((R)[3])       \
                 : "r"(addr))
#define MMA_S8(C, A0, A1, A2, A3, B0, B1)                                       \
    asm volatile("mma.sync.aligned.m16n8k32.row.col.s32.s8.s8.s32 "             \
                 "{%0,%1,%2,%3},{%4,%5,%6,%7},{%8,%9},{%0,%1,%2,%3};"           \
                 : "+r"((C)[0]), "+r"((C)[1]), "+r"((C)[2]), "+r"((C)[3])       \
                 : "r"(A0), "r"(A1), "r"(A2), "r"(A3), "r"(B0), "r"(B1))

__device__ __forceinline__ uint32_t smem_u32(const void* p) {
    uint32_t a;
    asm("{ .reg .u64 t; cvta.to.shared.u64 t, %1; cvt.u32.u64 %0, t; }" : "=r"(a) : "l"(p));
    return a;
}
__device__ __forceinline__ uint4 v4op(uint4 a, uint4 b, bool add) {
    uint4 r;
    if (add) { r.x = __vadd4(a.x, b.x); r.y = __vadd4(a.y, b.y);
               r.z = __vadd4(a.z, b.z); r.w = __vadd4(a.w, b.w); }
    else     { r.x = __vsub4(a.x, b.x); r.y = __vsub4(a.y, b.y);
               r.z = __vsub4(a.z, b.z); r.w = __vsub4(a.w, b.w); }
    return r;
}

#define B_STAGE 4608                        // combined V: 32 rows x 144B
#define RAW_STAGE 16384                     // raw quads: 256 threads x 64B
// q-permuted slot: 8 lanes of an LDS.128 phase hit 8 distinct 16B banks
#define RAW_SLOT(tid_, q_) ((tid_) * 64 + ((((q_) + ((tid_) >> 1)) & 3) << 4))

// ---------------- main kernel ----------------
__global__ __launch_bounds__(256, 2)
void wino_kernel(float* __restrict__ out)
{
    __shared__ __align__(16) signed char rawB[2 * RAW_STAGE];   // 32768 B
    __shared__ __align__(16) signed char comb[3 * B_STAGE];     // 13824 B
    const uint32_t rb0 = smem_u32(rawB);
    const uint32_t cb0 = smem_u32(comb);

    const int tid  = threadIdx.x;
    const int lane = tid & 31;
    const int wid  = tid >> 5;
    const int warp_m = wid >> 1;
    const int warp_n = wid & 1;
    const int coB = blockIdx.y;
    const int img = blockIdx.x / 29;
    const int ty  = blockIdx.x % 29;

    const int btx = tid >> 3, bcg = tid & 7;
    const signed char* const pb = g_p8 +
        (((size_t)img * 60 + 2 * ty) * PX + 2 * btx) * 128 + bcg * 16;

    const signed char* const aw = g_Ufrag + (size_t)(coB * 32 + warp_m * 8) * 512 + lane * 16;

    const uint32_t bOff = (uint32_t)(
        (warp_n * 16 + (lane & 7) + ((lane >> 4) << 3)) * 144 + ((lane >> 3) & 1) * 16);

    int OUT[2][2][4][4];
#pragma unroll
    for (int a = 0; a < 2; a++)
#pragma unroll
        for (int b = 0; b < 2; b++)
#pragma unroll
            for (int c = 0; c < 4; c++)
#pragma unroll
                for (int d = 0; d < 4; d++) OUT[a][b][c][d] = 0;

    // issue 4 cp.async raw quads for tap t into raw stage rs
    auto cpRawB = [&](int t, int rs) {
        const int i = t >> 2, j = t & 3;
        const int ya = (i == 0) ? 0 : (i == 2) ? 2 : 1;
        const int yb = (i == 3) ? 3 : (i == 2) ? 1 : 2;
        const int xa = (j == 0) ? 0 : (j == 2) ? 2 : 1;
        const int xb = (j == 3) ? 3 : (j == 2) ? 1 : 2;
        const uint32_t d0 = rb0 + rs * RAW_STAGE;
        CP16(d0 + RAW_SLOT(tid, 0), pb + (ya * PX + xa) * 128);
        CP16(d0 + RAW_SLOT(tid, 1), pb + (yb * PX + xa) * 128);
        CP16(d0 + RAW_SLOT(tid, 2), pb + (ya * PX + xb) * 128);
        CP16(d0 + RAW_SLOT(tid, 3), pb + (yb * PX + xb) * 128);
    };

    // read raw (own slots), combine, store V into combined stage cs
    auto combB = [&](int t, int cs, int rs) {
        const int i = t >> 2, j = t & 3;
        const signed char* r0 = rawB + rs * RAW_STAGE;
        uint4 daa = *(const uint4*)(r0 + RAW_SLOT(tid, 0));
        uint4 dba = *(const uint4*)(r0 + RAW_SLOT(tid, 1));
        uint4 dab = *(const uint4*)(r0 + RAW_SLOT(tid, 2));
        uint4 dbb = *(const uint4*)(r0 + RAW_SLOT(tid, 3));
        uint4 ea = v4op(daa, dba, i == 1);
        uint4 eb = v4op(dab, dbb, i == 1);
        uint4 v  = v4op(ea, eb, j == 1);
        *(uint4*)(comb + cs * B_STAGE + btx * 144 + bcg * 16) = v;
    };

    // ---------------- prologue ----------------
    cpRawB(0, 0); CP_COMMIT();
    CP_WAIT0();
    combB(0, 0, 0);
    __syncthreads();

    // ---------------- tap loop: one barrier per tap ----------------
#pragma unroll 1
    for (int t = 0; t < 16; t++) {
        if (t < 15) { cpRawB(t + 1, (t + 1) & 1); }
        CP_COMMIT();                          // uniform group accounting

        int Macc[2][2][4];
#pragma unroll
        for (int a = 0; a < 2; a++)
#pragma unroll
            for (int b = 0; b < 2; b++)
#pragma unroll
                for (int c = 0; c < 4; c++) Macc[a][b][c] = 0;

        const uint32_t sb = cb0 + (t % 3) * B_STAGE + bOff;
        const signed char* const at = aw + (size_t)t * 32768;
#pragma unroll
        for (int ks = 0; ks < 4; ks++) {
            uint4 a0 = *(const uint4*)(at + ks * 512);
            uint4 a1 = *(const uint4*)(at + (4 + ks) * 512);
            unsigned bf[4];
            LDSM_X4(bf, sb + ks * 32);
#pragma unroll
            for (int nj = 0; nj < 2; nj++) {
                MMA_S8(Macc[0][nj], a0.x, a0.y, a0.z, a0.w, bf[nj * 2], bf[nj * 2 + 1]);
                MMA_S8(Macc[1][nj], a1.x, a1.y, a1.z, a1.w, bf[nj * 2], bf[nj * 2 + 1]);
            }
        }

        // integer output combine: w = 4*a[y][i]*a[x][j] products, /4 -> int
        const int i = t >> 2, j = t & 3;
        const int wy0 = (i == 0) ? 4 : (i == 3) ? 0 : 2;
        const int wy1 = (i == 0) ? 0 : (i == 1) ? 2 : (i == 2) ? -2 : -4;
        const int wx0 = (j == 0) ? 4 : (j == 3) ? 0 : 2;
        const int wx1 = (j == 0) ? 0 : (j == 1) ? 2 : (j == 2) ? -2 : -4;
        const int w00 = (wy0 * wx0) / 4, w01 = (wy0 * wx1) / 4;
        const int w10 = (wy1 * wx0) / 4, w11 = (wy1 * wx1) / 4;
#pragma unroll
        for (int mi = 0; mi < 2; mi++)
#pragma unroll
            for (int nj = 0; nj < 2; nj++)
#pragma unroll
                for (int r = 0; r < 4; r++) {
                    const int f = Macc[mi][nj][r];
                    OUT[mi][nj][r][0] += w00 * f;
                    OUT[mi][nj][r][1] += w01 * f;
                    OUT[mi][nj][r][2] += w10 * f;
                    OUT[mi][nj][r][3] += w11 * f;
                }

        if (t < 15) {
            CP_WAIT0();                       // raw(t+1) landed (hidden by MMAs)
            combB(t + 1, (t + 1) % 3, (t + 1) & 1);
        }
        __syncthreads();                      // combined stage handoff
    }

    // ---------------- epilogue: scale by 1/4 (exact) and store ----------------
    const int g  = lane >> 2;
    const int tg = lane & 3;
#pragma unroll
    for (int mi = 0; mi < 2; mi++)
#pragma unroll
        for (int nj = 0; nj < 2; nj++)
#pragma unroll
            for (int r = 0; r < 4; r++) {
                const int tx = warp_n * 16 + nj * 8 + tg * 2 + (r & 1);
                if (tx >= 31) continue;
                const int co = coB * 128 + warp_m * 32 + mi * 16 + g + ((r >= 2) ? 8 : 0);
                float* ob = out + (((size_t)(img * 256 + co) * OH + 2 * ty) * OW + 2 * tx);
                *(float2*)ob        = make_float2(OUT[mi][nj][r][0] * 0.25f,
                                                  OUT[mi][nj][r][1] * 0.25f);
                *(float2*)(ob + OW) = make_float2(OUT[mi][nj][r][2] * 0.25f,
                                                  OUT[mi][nj][r][3] * 0.25f);
            }
}

extern "C" void kernel_launch(void* const* d_in, const int* in_sizes, int n_in,
                              void* d_out, int out_size)
{
    const float* inp = (const float*)d_in[0];
    const float* wgt = (const float*)d_in[1];
    float* out = (float*)d_out;

    prep_all<<<1920 + 2048, 256>>>(inp, wgt);
    wino_kernel<<<dim3(32 * 29, 2), 256>>>(out);
}

// round 15
// speedup vs baseline: 1.4378x; 1.4378x over previous
#include <cuda_runtime.h>
#include <cstdint>

// DirectConv2d full cross-correlation (pad=2) via Winograd F(2x2,3x3), int8 IMMA.
//   inp [32,128,56,60] f32 (0..3), wgt [256,128,3,3] f32 (0..2), out [32,256,58,62] f32
//
// U = Ghat g Ghat^T (|U|<=18, s8), V = B^T d B (|V|<=12, s8),
// out = (1/4) * sum_t w_t M_t, integer w in {0,+-1,+-2,+-4} — all exact, rel_err 0.
//
// R15 vs R13 (190us main): taps grouped by row-index i — one gather (8 LDG.128)
// + one barrier serves 4 taps (V stages share row-combined e(x) vectors).
// A fragments direct-from-global (R13, validated); integer OUT combine (R14).

#define OH 58
#define OW 62
#define PX 66

__device__ __align__(16) signed char g_p8[(size_t)32 * 60 * PX * 128];   // 16.2 MB
__device__ __align__(16) signed char g_Ufrag[16 * 2 * 4 * 2 * 4 * 512];  // 512 KB

// ---------------- combined pre-pass (identical to R13/R14, validated) ----------------
__global__ __launch_bounds__(256)
void prep_all(const float* __restrict__ inp, const float* __restrict__ wgt)
{
    if (blockIdx.x >= 1920) {
        int idx = (blockIdx.x - 1920) * 256 + threadIdx.x;
        int ci = idx & 127;
        int co = (idx >> 7) & 255;
        int t  = idx >> 15;
        int i = t >> 2, j = t & 3;
        const float* g = wgt + (size_t)(co * 128 + ci) * 9;
        float hv[3];
#pragma unroll
        for (int kw = 0; kw < 3; kw++) {
            float g0 = g[kw], g1 = g[3 + kw], g2 = g[6 + kw];
            hv[kw] = (i == 0) ? g0 : (i == 1) ? g0 + g1 + g2
                   : (i == 2) ? g0 - g1 + g2 : g2;
        }
        float u = (j == 0) ? hv[0] : (j == 1) ? hv[0] + hv[1] + hv[2]
                : (j == 2) ? hv[0] - hv[1] + hv[2] : hv[2];
        int coB = co >> 7, wm = (co >> 5) & 3;
        int r5 = co & 31,  mi = r5 >> 4, rr = r5 & 15;
        int qb = rr >> 3,  lh = rr & 7;
        int ks = ci >> 5,  cr = ci & 31;
        int qh = cr >> 4,  cl = cr & 15;
        int l  = lh * 4 + (cl >> 2);
        int q  = qh * 2 + qb;
        g_Ufrag[(size_t)(((((t * 2 + coB) * 4 + wm) * 2 + mi) * 4 + ks)) * 512
                + l * 16 + q * 4 + (cl & 3)] = (signed char)__float2int_rn(u);
        return;
    }
    __shared__ signed char sh[PX][144];
    const int y   = blockIdx.x % 60;
    const int img = blockIdx.x / 60;
    const int tid = threadIdx.x;
    const int ih  = y - 2;
    const bool rowOK = (unsigned)ih < 56u;
    for (int it = 0; it < 33; it++) {
        int idx = it * 256 + tid;
        int x  = idx % PX;
        int ci = idx / PX;
        int iw = x - 2;
        float v = 0.0f;
        if (rowOK && (unsigned)iw < 60u)
            v = inp[((size_t)(img * 128 + ci) * 56 + ih) * 60 + iw];
        sh[x][ci] = (signed char)__float2int_rn(v);
    }
    __syncthreads();
    signed char* const ob = g_p8 + ((size_t)(img * 60 + y) * PX) * 128;
    for (int it = 0; it < 3; it++) {
        int idx = it * 256 + tid;
        if (idx >= PX * 8) break;
        int x = idx >> 3, c16 = idx & 7;
        *(uint4*)(ob + x * 128 + c16 * 16) = *(const uint4*)(&sh[x][c16 * 16]);
    }
}

// ---------------- PTX helpers ----------------
#define LDSM_X4(R, addr)                                                        \
    asm volatile("ldmatrix.sync.aligned.m8n8.x4.shared.b16 {%0,%1,%2,%3}, [%4];"\
                 : "=r"((R)[0]), "=r"((R)[1]), "=r"((R)[2]), "=r"((R)[3])       \
                 : "r"(addr))
#define MMA_S8(C, A0, A1, A2, A3, B0, B1)                                       \
    asm volatile("mma.sync.aligned.m16n8k32.row.col.s32.s8.s8.s32 "             \
                 "{%0,%1,%2,%3},{%4,%5,%6,%7},{%8,%9},{%0,%1,%2,%3};"           \
                 : "+r"((C)[0]), "+r"((C)[1]), "+r"((C)[2]), "+r"((C)[3])       \
                 : "r"(A0), "r"(A1), "r"(A2), "r"(A3), "r"(B0), "r"(B1))

__device__ __forceinline__ uint32_t smem_u32(const void* p) {
    uint32_t a;
    asm("{ .reg .u64 t; cvta.to.shared.u64 t, %1; cvt.u32.u64 %0, t; }" : "=r"(a) : "l"(p));
    return a;
}
__device__ __forceinline__ uint4 v4op(uint4 a, uint4 b, bool add) {
    uint4 r;
    if (add) { r.x = __vadd4(a.x, b.x); r.y = __vadd4(a.y, b.y);
               r.z = __vadd4(a.z, b.z); r.w = __vadd4(a.w, b.w); }
    else     { r.x = __vsub4(a.x, b.x); r.y = __vsub4(a.y, b.y);
               r.z = __vsub4(a.z, b.z); r.w = __vsub4(a.w, b.w); }
    return r;
}

#define B_STAGE 4608              // one V tile: 32 rows x 144B
#define GRP     (4 * B_STAGE)     // 4 V stages per i-group

// ---------------- main kernel ----------------
__global__ __launch_bounds__(256, 2)
void wino_kernel(float* __restrict__ out)
{
    __shared__ __align__(16) signed char comb[2 * GRP];   // 36864 B
    const uint32_t cb0 = smem_u32(comb);

    const int tid  = threadIdx.x;
    const int lane = tid & 31;
    const int wid  = tid >> 5;
    const int warp_m = wid >> 1;
    const int warp_n = wid & 1;
    const int coB = blockIdx.y;
    const int img = blockIdx.x / 29;
    const int ty  = blockIdx.x % 29;

    const int btx = tid >> 3, bcg = tid & 7;
    const signed char* const pb = g_p8 +
        (((size_t)img * 60 + 2 * ty) * PX + 2 * btx) * 128 + bcg * 16;

    const signed char* const aw = g_Ufrag + (size_t)(coB * 32 + warp_m * 8) * 512 + lane * 16;

    const uint32_t bOff = (uint32_t)(
        (warp_n * 16 + (lane & 7) + ((lane >> 4) << 3)) * 144 + ((lane >> 3) & 1) * 16);

    int OUT[2][2][4][4];
#pragma unroll
    for (int a = 0; a < 2; a++)
#pragma unroll
        for (int b = 0; b < 2; b++)
#pragma unroll
            for (int c = 0; c < 4; c++)
#pragma unroll
                for (int d = 0; d < 4; d++) OUT[a][b][c][d] = 0;

    // fill ALL 4 V stages of i-group i into buffer buf (8 LDG + 8 v4ops + 4 STS)
    auto fillGroup = [&](int i, int buf) {
        const int ya = (i == 0) ? 0 : (i == 2) ? 2 : 1;
        const int yb = (i == 3) ? 3 : (i == 2) ? 1 : 2;
        uint4 e[4];
#pragma unroll
        for (int x = 0; x < 4; x++) {
            uint4 da = *(const uint4*)(pb + (ya * PX + x) * 128);
            uint4 db = *(const uint4*)(pb + (yb * PX + x) * 128);
            e[x] = v4op(da, db, i == 1);
        }
        // j combos: j0=e0-e2, j1=e1+e2, j2=e2-e1, j3=e1-e3
        signed char* base = comb + buf * GRP + btx * 144 + bcg * 16;
        *(uint4*)(base)               = v4op(e[0], e[2], false);
        *(uint4*)(base + B_STAGE)     = v4op(e[1], e[2], true);
        *(uint4*)(base + 2 * B_STAGE) = v4op(e[2], e[1], false);
        *(uint4*)(base + 3 * B_STAGE) = v4op(e[1], e[3], false);
    };

    // ---------------- group loop: ONE barrier + ONE gather per 4 taps ----------------
    fillGroup(0, 0);
    __syncthreads();
#pragma unroll 1
    for (int g = 0; g < 4; g++) {
        if (g < 3) fillGroup(g + 1, (g + 1) & 1);   // writes buf^1; compute reads buf

        const int wy0 = (g == 0) ? 4 : (g == 3) ? 0 : 2;
        const int wy1 = (g == 0) ? 0 : (g == 1) ? 2 : (g == 2) ? -2 : -4;
        const uint32_t gbase = cb0 + (g & 1) * GRP + bOff;
        const signed char* const ag = aw + (size_t)(g * 4) * 32768;

#pragma unroll
        for (int j = 0; j < 4; j++) {
            int Macc[2][2][4];
#pragma unroll
            for (int a = 0; a < 2; a++)
#pragma unroll
                for (int b = 0; b < 2; b++)
#pragma unroll
                    for (int c = 0; c < 4; c++) Macc[a][b][c] = 0;

            const uint32_t sb = gbase + j * B_STAGE;
            const signed char* const at = ag + (size_t)j * 32768;
#pragma unroll
            for (int ks = 0; ks < 4; ks++) {
                uint4 a0 = *(const uint4*)(at + ks * 512);
                uint4 a1 = *(const uint4*)(at + (4 + ks) * 512);
                unsigned bf[4];
                LDSM_X4(bf, sb + ks * 32);
#pragma unroll
                for (int nj = 0; nj < 2; nj++) {
                    MMA_S8(Macc[0][nj], a0.x, a0.y, a0.z, a0.w, bf[nj * 2], bf[nj * 2 + 1]);
                    MMA_S8(Macc[1][nj], a1.x, a1.y, a1.z, a1.w, bf[nj * 2], bf[nj * 2 + 1]);
                }
            }

            // integer output combine (w = 4*a_y*a_x / 4; exact)
            const int wx0 = (j == 0) ? 4 : (j == 3) ? 0 : 2;
            const int wx1 = (j == 0) ? 0 : (j == 1) ? 2 : (j == 2) ? -2 : -4;
            const int w00 = (wy0 * wx0) >> 2, w01 = (wy0 * wx1) / 4;
            const int w10 = (wy1 * wx0) / 4,  w11 = (wy1 * wx1) / 4;
#pragma unroll
            for (int mi = 0; mi < 2; mi++)
#pragma unroll
                for (int nj = 0; nj < 2; nj++)
#pragma unroll
                    for (int r = 0; r < 4; r++) {
                        const int f = Macc[mi][nj][r];
                        OUT[mi][nj][r][0] += w00 * f;
                        OUT[mi][nj][r][1] += w01 * f;
                        OUT[mi][nj][r][2] += w10 * f;
                        OUT[mi][nj][r][3] += w11 * f;
                    }
        }
        __syncthreads();            // buf handoff (fill g+1 done; compute g done)
    }

    // ---------------- epilogue: x0.25 (exact) and store ----------------
    const int g  = lane >> 2;
    const int tg = lane & 3;
#pragma unroll
    for (int mi = 0; mi < 2; mi++)
#pragma unroll
        for (int nj = 0; nj < 2; nj++)
#pragma unroll
            for (int r = 0; r < 4; r++) {
                const int tx = warp_n * 16 + nj * 8 + tg * 2 + (r & 1);
                if (tx >= 31) continue;
                const int co = coB * 128 + warp_m * 32 + mi * 16 + g + ((r >= 2) ? 8 : 0);
                float* ob = out + (((size_t)(img * 256 + co) * OH + 2 * ty) * OW + 2 * tx);
                *(float2*)ob        = make_float2(OUT[mi][nj][r][0] * 0.25f,
                                                  OUT[mi][nj][r][1] * 0.25f);
                *(float2*)(ob + OW) = make_float2(OUT[mi][nj][r][2] * 0.25f,
                                                  OUT[mi][nj][r][3] * 0.25f);
            }
}

extern "C" void kernel_launch(void* const* d_in, const int* in_sizes, int n_in,
                              void* d_out, int out_size)
{
    const float* inp = (const float*)d_in[0];
    const float* wgt = (const float*)d_in[1];
    float* out = (float*)d_out;

    prep_all<<<1920 + 2048, 256>>>(inp, wgt);
    wino_kernel<<<dim3(32 * 29, 2), 256>>>(out);
}